// round 2
// baseline (speedup 1.0000x reference)
#include <cuda_runtime.h>

#define NATOMS 10000
#define NPAIRS 320000
#define FDIM 128
#define KDIM 64
#define NB 5
#define NRI 3
#define NRA 2
#define NRO 1

// ---------------- scratch (device globals; no allocs allowed) ----------------
__device__ float g_rbf[NPAIRS * KDIM];     // 82 MB
__device__ float g_x [NATOMS * FDIM];
__device__ float g_xj[NATOMS * FDIM];
__device__ float g_m [NATOMS * FDIM];
__device__ float g_t [NATOMS * FDIM];
__device__ float g_o [NATOMS * FDIM];
__device__ float g_Ea[NATOMS];
__device__ float g_Qa[NATOMS];
__device__ float g_l2[NATOMS * 2];
__device__ float g_nh;

// shifted softplus: softplus(x) - ln2, numerically stable
__device__ __forceinline__ float actf(float x) {
    return fmaxf(x, 0.f) + log1pf(__expf(-fabsf(x))) - 0.69314718055994531f;
}

__device__ __forceinline__ void red_add_f4(float* p, float4 v) {
    asm volatile("red.global.add.v4.f32 [%0], {%1,%2,%3,%4};"
                 :: "l"(p), "f"(v.x), "f"(v.y), "f"(v.z), "f"(v.w) : "memory");
}

// ---------------- init: x = embeddings[Z] ----------------
__global__ void init_kernel(const int* __restrict__ Z, const float* __restrict__ emb,
                            float* __restrict__ x) {
    int idx = blockIdx.x * blockDim.x + threadIdx.x;
    if (idx < NATOMS * FDIM) {
        int n = idx >> 7, f = idx & 127;
        x[idx] = emb[Z[n] * FDIM + f];
    }
}

// ---------------- pair: Dij + rbf ----------------
__global__ void pair_kernel(const float* __restrict__ R, const int* __restrict__ idx_i,
                            const int* __restrict__ idx_j, const float* __restrict__ cent,
                            const float* __restrict__ wid, float* __restrict__ rbf,
                            float* __restrict__ Dij_out) {
    int gid = blockIdx.x * blockDim.x + threadIdx.x;
    int p = gid >> 6, k = gid & 63;
    if (p >= NPAIRS) return;
    int i = idx_i[p], j = idx_j[p];
    float dx = R[i * 3 + 0] - R[j * 3 + 0];
    float dy = R[i * 3 + 1] - R[j * 3 + 1];
    float dz = R[i * 3 + 2] - R[j * 3 + 2];
    float D = sqrtf(fmaxf(dx * dx + dy * dy + dz * dz, 0.f));
    if (k == 0) Dij_out[p] = D;
    float xr = D * 0.1f;
    float cut = 0.f;
    if (xr < 1.f) {
        float x3 = xr * xr * xr, x4 = x3 * xr, x5 = x4 * xr;
        cut = 1.f - 6.f * x5 + 15.f * x4 - 10.f * x3;
    }
    float ed = __expf(-D);
    float t = ed - cent[k];
    rbf[p * KDIM + k] = cut * __expf(-wid[k] * t * t);
}

// ---------------- GEMM: C = epi( act?(A) @ W + bias ) ----------------
// EPI: 0 plain, 1 C = base + ..., 2 C = uvec*base + ...
#define TR 64
#define AP 68
#define GSMEM (FDIM * FDIM * 4 + FDIM * AP * 4)

template <int PRE, int POST, int EPI>
__global__ void __launch_bounds__(128) gemm128(
    const float* __restrict__ A, const float* __restrict__ W,
    const float* __restrict__ bias, const float* __restrict__ base,
    const float* __restrict__ uvec, float* __restrict__ C, int nrows) {
    extern __shared__ float sm[];
    float* Ws = sm;                 // [128][128]
    float* As = sm + FDIM * FDIM;   // [128][AP] transposed A tile
    const int tid = threadIdx.x;
    const int r0 = blockIdx.x * TR;

    {   // load full W (64KB), coalesced float4
        const float4* Wv = (const float4*)W;
        float4* Wsv = (float4*)Ws;
#pragma unroll
        for (int i = 0; i < 32; i++) Wsv[tid + i * 128] = Wv[tid + i * 128];
    }
    {   // load A tile (64 rows), transpose into As[k][r]
#pragma unroll
        for (int i = 0; i < 16; i++) {
            int v = tid + i * 128;
            int r = v & 63, kq = v >> 6;
            int row = r0 + r;
            float4 av = make_float4(0.f, 0.f, 0.f, 0.f);
            if (row < nrows) av = *(const float4*)(A + row * FDIM + kq * 4);
            if (PRE) { av.x = actf(av.x); av.y = actf(av.y); av.z = actf(av.z); av.w = actf(av.w); }
            As[(kq * 4 + 0) * AP + r] = av.x;
            As[(kq * 4 + 1) * AP + r] = av.y;
            As[(kq * 4 + 2) * AP + r] = av.z;
            As[(kq * 4 + 3) * AP + r] = av.w;
        }
    }
    __syncthreads();

    const int rg = tid >> 4;   // 8 row-groups of 8 rows
    const int cg = tid & 15;   // 16 col-groups of 8 cols
    float acc[8][8];
#pragma unroll
    for (int i = 0; i < 8; i++)
#pragma unroll
        for (int j = 0; j < 8; j++) acc[i][j] = 0.f;

#pragma unroll 8
    for (int k = 0; k < 128; k++) {
        float a[8], w[8];
        *(float4*)&a[0] = *(const float4*)&As[k * AP + rg * 8];
        *(float4*)&a[4] = *(const float4*)&As[k * AP + rg * 8 + 4];
        *(float4*)&w[0] = *(const float4*)&Ws[k * 128 + cg * 8];
        *(float4*)&w[4] = *(const float4*)&Ws[k * 128 + cg * 8 + 4];
#pragma unroll
        for (int i = 0; i < 8; i++)
#pragma unroll
            for (int j = 0; j < 8; j++) acc[i][j] = fmaf(a[i], w[j], acc[i][j]);
    }

    const int cb = cg * 8;
    float bv[8];
#pragma unroll
    for (int j = 0; j < 8; j++) bv[j] = bias[cb + j];
    float uv[8];
    if (EPI == 2) {
#pragma unroll
        for (int j = 0; j < 8; j++) uv[j] = uvec[cb + j];
    }
#pragma unroll
    for (int i = 0; i < 8; i++) {
        int row = r0 + rg * 8 + i;
        if (row < nrows) {
            float v[8];
#pragma unroll
            for (int j = 0; j < 8; j++) {
                float t = acc[i][j] + bv[j];
                if (POST) t = actf(t);
                v[j] = t;
            }
            if (EPI >= 1) {
                float4 b0 = *(const float4*)&base[row * FDIM + cb];
                float4 b1 = *(const float4*)&base[row * FDIM + cb + 4];
                if (EPI == 1) {
                    v[0] += b0.x; v[1] += b0.y; v[2] += b0.z; v[3] += b0.w;
                    v[4] += b1.x; v[5] += b1.y; v[6] += b1.z; v[7] += b1.w;
                } else {
                    v[0] += uv[0] * b0.x; v[1] += uv[1] * b0.y;
                    v[2] += uv[2] * b0.z; v[3] += uv[3] * b0.w;
                    v[4] += uv[4] * b1.x; v[5] += uv[5] * b1.y;
                    v[6] += uv[6] * b1.z; v[7] += uv[7] * b1.w;
                }
            }
            *(float4*)&C[row * FDIM + cb]     = make_float4(v[0], v[1], v[2], v[3]);
            *(float4*)&C[row * FDIM + cb + 4] = make_float4(v[4], v[5], v[6], v[7]);
        }
    }
}

// ---------------- message: m[idx_i] += (rbf @ k2f) * xj[idx_j], fused ----------------
__global__ void __launch_bounds__(256) message_kernel(
    const float* __restrict__ rbf, const float* __restrict__ k2f,
    const float* __restrict__ xj, const int* __restrict__ idx_i,
    const int* __restrict__ idx_j, float* __restrict__ m) {
    __shared__ float k2fs[KDIM * FDIM];   // 32 KB
    __shared__ float rbfs[8 * KDIM];      // 2 KB
    const int tid = threadIdx.x;
    {
        const float4* kv = (const float4*)k2f;
        float4* ksv = (float4*)k2fs;
#pragma unroll
        for (int i = 0; i < 8; i++) ksv[tid + i * 256] = kv[tid + i * 256];
    }
    const int fg = tid & 31;   // feature group: 4 consecutive features
    const int ps = tid >> 5;   // pair slot 0..7
    const int nch = (NPAIRS + 7) >> 3;
    for (int ch = blockIdx.x; ch < nch; ch += gridDim.x) {
        int base = ch * 8;
        __syncthreads();
#pragma unroll
        for (int i = 0; i < 2; i++) {
            int t = tid + i * 256;
            int pp = base + (t >> 6);
            rbfs[t] = (pp < NPAIRS) ? rbf[pp * KDIM + (t & 63)] : 0.f;
        }
        __syncthreads();
        int p = base + ps;
        if (p < NPAIRS) {
            int i = idx_i[p], j = idx_j[p];
            float4 g = make_float4(0.f, 0.f, 0.f, 0.f);
            const float* rr = &rbfs[ps * KDIM];
#pragma unroll
            for (int k = 0; k < KDIM; k++) {
                float r = rr[k];
                float4 w = *(const float4*)&k2fs[k * FDIM + fg * 4];
                g.x = fmaf(r, w.x, g.x); g.y = fmaf(r, w.y, g.y);
                g.z = fmaf(r, w.z, g.z); g.w = fmaf(r, w.w, g.w);
            }
            float4 xv = *(const float4*)(xj + j * FDIM + fg * 4);
            red_add_f4(m + i * FDIM + fg * 4,
                       make_float4(g.x * xv.x, g.y * xv.y, g.z * xv.z, g.w * xv.w));
        }
    }
}

// ---------------- output block: Ea/Qa/nhloss per atom ----------------
__global__ void outblock_kernel(const float* __restrict__ o, const float* __restrict__ ow,
                                float* __restrict__ Ea, float* __restrict__ Qa,
                                float* __restrict__ last2, float* __restrict__ nh, int bpos) {
    int n = blockIdx.x, tid = threadIdx.x;
    float a = actf(o[n * FDIM + tid]);
    float e = a * ow[tid * 2], q = a * ow[tid * 2 + 1];
#pragma unroll
    for (int s = 16; s; s >>= 1) {
        e += __shfl_xor_sync(0xffffffffu, e, s);
        q += __shfl_xor_sync(0xffffffffu, q, s);
    }
    __shared__ float se[4], sq[4];
    if ((tid & 31) == 0) { se[tid >> 5] = e; sq[tid >> 5] = q; }
    __syncthreads();
    if (tid == 0) {
        e = se[0] + se[1] + se[2] + se[3];
        q = sq[0] + sq[1] + sq[2] + sq[3];
        Ea[n] += e; Qa[n] += q;
        float e2 = e * e, q2 = q * q;
        if (bpos) {
            float le = last2[2 * n], lq = last2[2 * n + 1];
            atomicAdd(nh, e2 / (e2 + le + 1e-7f) + q2 / (q2 + lq + 1e-7f));
        }
        last2[2 * n] = e2; last2[2 * n + 1] = q2;
    }
}

// ---------------- final: scale/shift + nhloss ----------------
__global__ void final_kernel(const int* __restrict__ Z, const float* __restrict__ Ea,
                             const float* __restrict__ Qa, const float* __restrict__ nh,
                             const float* __restrict__ Es, const float* __restrict__ Eh,
                             const float* __restrict__ Qs, const float* __restrict__ Qh,
                             float* __restrict__ out) {
    int n = blockIdx.x * blockDim.x + threadIdx.x;
    if (n < NATOMS) {
        int z = Z[n];
        out[n]          = Es[z] * Ea[n] + Eh[z];
        out[NATOMS + n] = Qs[z] * Qa[n] + Qh[z];
    }
    if (n == 0) out[2 * NATOMS + NPAIRS] = *nh / (2.f * NATOMS);
}

// ---------------- launch ----------------
extern "C" void kernel_launch(void* const* d_in, const int* in_sizes, int n_in,
                              void* d_out, int out_size) {
    const int*   Z      = (const int*)  d_in[0];
    const float* R      = (const float*)d_in[1];
    const int*   idx_i  = (const int*)  d_in[2];
    const int*   idx_j  = (const int*)  d_in[3];
    const float* emb    = (const float*)d_in[4];
    const float* cent   = (const float*)d_in[5];
    const float* wid    = (const float*)d_in[6];
    const float* k2f    = (const float*)d_in[7];
    const float* Wi     = (const float*)d_in[8];
    const float* bi     = (const float*)d_in[9];
    const float* Wj     = (const float*)d_in[10];
    const float* bj     = (const float*)d_in[11];
    const float* riW1   = (const float*)d_in[12];
    const float* rib1   = (const float*)d_in[13];
    const float* riW2   = (const float*)d_in[14];
    const float* rib2   = (const float*)d_in[15];
    const float* dW     = (const float*)d_in[16];
    const float* db     = (const float*)d_in[17];
    const float* u      = (const float*)d_in[18];
    const float* raW1   = (const float*)d_in[19];
    const float* rab1   = (const float*)d_in[20];
    const float* raW2   = (const float*)d_in[21];
    const float* rab2   = (const float*)d_in[22];
    const float* roW1   = (const float*)d_in[23];
    const float* rob1   = (const float*)d_in[24];
    const float* roW2   = (const float*)d_in[25];
    const float* rob2   = (const float*)d_in[26];
    const float* outW   = (const float*)d_in[27];
    const float* Escale = (const float*)d_in[28];
    const float* Eshift = (const float*)d_in[29];
    const float* Qscale = (const float*)d_in[30];
    const float* Qshift = (const float*)d_in[31];
    float* out = (float*)d_out;

    float *rbf, *x, *xjb, *m, *t, *o, *Ea, *Qa, *l2, *nh;
    cudaGetSymbolAddress((void**)&rbf, g_rbf);
    cudaGetSymbolAddress((void**)&x,   g_x);
    cudaGetSymbolAddress((void**)&xjb, g_xj);
    cudaGetSymbolAddress((void**)&m,   g_m);
    cudaGetSymbolAddress((void**)&t,   g_t);
    cudaGetSymbolAddress((void**)&o,   g_o);
    cudaGetSymbolAddress((void**)&Ea,  g_Ea);
    cudaGetSymbolAddress((void**)&Qa,  g_Qa);
    cudaGetSymbolAddress((void**)&l2,  g_l2);
    cudaGetSymbolAddress((void**)&nh,  g_nh);

    cudaFuncSetAttribute(gemm128<1,1,0>, cudaFuncAttributeMaxDynamicSharedMemorySize, GSMEM);
    cudaFuncSetAttribute(gemm128<0,0,1>, cudaFuncAttributeMaxDynamicSharedMemorySize, GSMEM);
    cudaFuncSetAttribute(gemm128<1,0,2>, cudaFuncAttributeMaxDynamicSharedMemorySize, GSMEM);

    cudaMemsetAsync(Ea, 0, NATOMS * sizeof(float));
    cudaMemsetAsync(Qa, 0, NATOMS * sizeof(float));
    cudaMemsetAsync(nh, 0, sizeof(float));

    init_kernel<<<(NATOMS * FDIM + 255) / 256, 256>>>(Z, emb, x);
    pair_kernel<<<(NPAIRS * KDIM + 255) / 256, 256>>>(R, idx_i, idx_j, cent, wid, rbf,
                                                      out + 2 * NATOMS);

    const int GB = (NATOMS + TR - 1) / TR;  // 157
    for (int b = 0; b < NB; b++) {
        // xi -> m directly (m = xi, then message scatter-adds)
        gemm128<1,1,0><<<GB,128,GSMEM>>>(x, Wi + b*16384, bi + b*128, nullptr, nullptr, m, NATOMS);
        gemm128<1,1,0><<<GB,128,GSMEM>>>(x, Wj + b*16384, bj + b*128, nullptr, nullptr, xjb, NATOMS);
        message_kernel<<<888,256>>>(rbf, k2f + b*KDIM*FDIM, xjb, idx_i, idx_j, m);
        for (int l = 0; l < NRI; l++) {
            int w = (b*NRI + l);
            gemm128<1,1,0><<<GB,128,GSMEM>>>(m, riW1 + w*16384, rib1 + w*128, nullptr, nullptr, t, NATOMS);
            gemm128<0,0,1><<<GB,128,GSMEM>>>(t, riW2 + w*16384, rib2 + w*128, m, nullptr, m, NATOMS);
        }
        // x = u*x + act(m)@dW + db
        gemm128<1,0,2><<<GB,128,GSMEM>>>(m, dW + b*16384, db + b*128, x, u + b*128, x, NATOMS);
        for (int l = 0; l < NRA; l++) {
            int w = (b*NRA + l);
            gemm128<1,1,0><<<GB,128,GSMEM>>>(x, raW1 + w*16384, rab1 + w*128, nullptr, nullptr, t, NATOMS);
            gemm128<0,0,1><<<GB,128,GSMEM>>>(t, raW2 + w*16384, rab2 + w*128, x, nullptr, x, NATOMS);
        }
        // output residual (NRO = 1): o = x + act(act(x)@W1+b1)@W2 + b2
        gemm128<1,1,0><<<GB,128,GSMEM>>>(x, roW1 + b*16384, rob1 + b*128, nullptr, nullptr, t, NATOMS);
        gemm128<0,0,1><<<GB,128,GSMEM>>>(t, roW2 + b*16384, rob2 + b*128, x, nullptr, o, NATOMS);
        outblock_kernel<<<NATOMS,128>>>(o, outW + b*FDIM*2, Ea, Qa, l2, nh, b);
    }
    final_kernel<<<(NATOMS + 255) / 256, 256>>>(Z, Ea, Qa, nh, Escale, Eshift,
                                                Qscale, Qshift, out);
}

// round 3
// speedup vs baseline: 1.2384x; 1.2384x over previous
#include <cuda_runtime.h>

#define NATOMS 10000
#define NPAIRS 320000
#define FDIM 128
#define KDIM 64
#define NB 5
#define NRI 3
#define NRA 2
#define NRO 1

#define TR 64
#define AP 68     // padded transposed-A row (floats)
#define HP 132    // padded h row (floats), row-major

#define SM_PLAIN ((16384 + 128 * AP) * 4)
#define SM_DUAL  ((32768 + 128 * AP) * 4)
#define SM_RES   ((32768 + 128 * AP + TR * HP) * 4)

// ---------------- scratch ----------------
__device__ float g_rbf[NPAIRS * KDIM];
__device__ float g_x [NATOMS * FDIM];
__device__ float g_xj[NATOMS * FDIM];
__device__ float g_m [NATOMS * FDIM];
__device__ float g_o [NATOMS * FDIM];
__device__ float g_Ea[NATOMS];
__device__ float g_Qa[NATOMS];
__device__ float g_l2[NATOMS * 2];
__device__ float g_nh;

__device__ __forceinline__ float actf(float x) {
    return fmaxf(x, 0.f) + log1pf(__expf(-fabsf(x))) - 0.69314718055994531f;
}

__device__ __forceinline__ void red_add_f4(float* p, float4 v) {
    asm volatile("red.global.add.v4.f32 [%0], {%1,%2,%3,%4};"
                 :: "l"(p), "f"(v.x), "f"(v.y), "f"(v.z), "f"(v.w) : "memory");
}

// ---------------- shared-memory loaders (256 threads) ----------------
__device__ __forceinline__ void load_W(const float* __restrict__ W, float* Ws, int tid) {
    const float4* Wv = (const float4*)W;
    float4* Wsv = (float4*)Ws;
#pragma unroll
    for (int i = 0; i < 16; i++) Wsv[tid + i * 256] = Wv[tid + i * 256];
}

template <int PRE>
__device__ __forceinline__ void load_Atr(const float* __restrict__ A, float* As,
                                         int tid, int r0, int nrows) {
#pragma unroll
    for (int i = 0; i < 8; i++) {
        int v = tid + i * 256;
        int r = v & 63, kq = v >> 6;
        int row = r0 + r;
        float4 av = make_float4(0.f, 0.f, 0.f, 0.f);
        if (row < nrows) av = *(const float4*)(A + row * FDIM + kq * 4);
        if (PRE) { av.x = actf(av.x); av.y = actf(av.y); av.z = actf(av.z); av.w = actf(av.w); }
        As[(kq * 4 + 0) * AP + r] = av.x;
        As[(kq * 4 + 1) * AP + r] = av.y;
        As[(kq * 4 + 2) * AP + r] = av.z;
        As[(kq * 4 + 3) * AP + r] = av.w;
    }
}

// ---------------- k-loops: 4 rows x 8 cols per thread ----------------
__device__ __forceinline__ void kloop128(const float* __restrict__ As,
                                         const float* __restrict__ Ws,
                                         int rg, int cg, float acc[4][8]) {
#pragma unroll
    for (int i = 0; i < 4; i++)
#pragma unroll
        for (int j = 0; j < 8; j++) acc[i][j] = 0.f;
    const float* ap = As + rg * 4;
    const float* wp = Ws + cg * 8;
#pragma unroll 8
    for (int k = 0; k < 128; k++) {
        float a[4], w[8];
        *(float4*)&a[0] = *(const float4*)(ap + k * AP);
        *(float4*)&w[0] = *(const float4*)(wp + k * 128);
        *(float4*)&w[4] = *(const float4*)(wp + k * 128 + 4);
#pragma unroll
        for (int i = 0; i < 4; i++)
#pragma unroll
            for (int j = 0; j < 8; j++) acc[i][j] = fmaf(a[i], w[j], acc[i][j]);
    }
}

__device__ __forceinline__ void kloop_h(const float* __restrict__ hs,
                                        const float* __restrict__ Ws,
                                        int rg, int cg, float acc[4][8]) {
#pragma unroll
    for (int i = 0; i < 4; i++)
#pragma unroll
        for (int j = 0; j < 8; j++) acc[i][j] = 0.f;
    const float* hp = hs + rg * 4 * HP;
    const float* wp = Ws + cg * 8;
#pragma unroll 8
    for (int k = 0; k < 128; k++) {
        float a[4], w[8];
        a[0] = hp[0 * HP + k]; a[1] = hp[1 * HP + k];
        a[2] = hp[2 * HP + k]; a[3] = hp[3 * HP + k];
        *(float4*)&w[0] = *(const float4*)(wp + k * 128);
        *(float4*)&w[4] = *(const float4*)(wp + k * 128 + 4);
#pragma unroll
        for (int i = 0; i < 4; i++)
#pragma unroll
            for (int j = 0; j < 8; j++) acc[i][j] = fmaf(a[i], w[j], acc[i][j]);
    }
}

// ---------------- dual GEMM: C1 = act(act(A)@W1+b1), C2 = act(act(A)@W2+b2) ----------------
__global__ void __launch_bounds__(256) gemm_dual(
    const float* __restrict__ A, const float* __restrict__ W1, const float* __restrict__ b1,
    const float* __restrict__ W2, const float* __restrict__ b2,
    float* __restrict__ C1, float* __restrict__ C2, int nrows) {
    extern __shared__ float sm[];
    float* Ws1 = sm;
    float* Ws2 = sm + 16384;
    float* As  = sm + 32768;
    const int tid = threadIdx.x;
    const int r0 = blockIdx.x * TR;
    load_W(W1, Ws1, tid);
    load_W(W2, Ws2, tid);
    load_Atr<1>(A, As, tid, r0, nrows);
    __syncthreads();
    const int rg = tid >> 4, cg = tid & 15, cb = cg * 8;
    float acc[4][8];

    kloop128(As, Ws1, rg, cg, acc);
    {
        float bv[8];
#pragma unroll
        for (int j = 0; j < 8; j++) bv[j] = b1[cb + j];
#pragma unroll
        for (int i = 0; i < 4; i++) {
            int row = r0 + rg * 4 + i;
            if (row < nrows) {
                float v[8];
#pragma unroll
                for (int j = 0; j < 8; j++) v[j] = actf(acc[i][j] + bv[j]);
                *(float4*)&C1[row * FDIM + cb]     = make_float4(v[0], v[1], v[2], v[3]);
                *(float4*)&C1[row * FDIM + cb + 4] = make_float4(v[4], v[5], v[6], v[7]);
            }
        }
    }
    kloop128(As, Ws2, rg, cg, acc);
    {
        float bv[8];
#pragma unroll
        for (int j = 0; j < 8; j++) bv[j] = b2[cb + j];
#pragma unroll
        for (int i = 0; i < 4; i++) {
            int row = r0 + rg * 4 + i;
            if (row < nrows) {
                float v[8];
#pragma unroll
                for (int j = 0; j < 8; j++) v[j] = actf(acc[i][j] + bv[j]);
                *(float4*)&C2[row * FDIM + cb]     = make_float4(v[0], v[1], v[2], v[3]);
                *(float4*)&C2[row * FDIM + cb + 4] = make_float4(v[4], v[5], v[6], v[7]);
            }
        }
    }
}

// ---------------- fused residual: C = A + act(act(A)@W1+b1)@W2 + b2 ----------------
__global__ void __launch_bounds__(256) gemm_resid(
    const float* __restrict__ A, const float* __restrict__ W1, const float* __restrict__ b1,
    const float* __restrict__ W2, const float* __restrict__ b2,
    float* __restrict__ C, int nrows) {
    extern __shared__ float sm[];
    float* Ws1 = sm;
    float* Ws2 = sm + 16384;
    float* As  = sm + 32768;
    float* hs  = sm + 32768 + 128 * AP;
    const int tid = threadIdx.x;
    const int r0 = blockIdx.x * TR;
    load_W(W1, Ws1, tid);
    load_W(W2, Ws2, tid);
    load_Atr<1>(A, As, tid, r0, nrows);
    __syncthreads();
    const int rg = tid >> 4, cg = tid & 15, cb = cg * 8;
    float acc[4][8];

    kloop128(As, Ws1, rg, cg, acc);
    __syncthreads();   // everyone done reading As / W1 region not touched; protects hs reuse timing
    {
        float bv[8];
#pragma unroll
        for (int j = 0; j < 8; j++) bv[j] = b1[cb + j];
#pragma unroll
        for (int i = 0; i < 4; i++) {
            int lr = rg * 4 + i;
            float v[8];
#pragma unroll
            for (int j = 0; j < 8; j++) v[j] = actf(acc[i][j] + bv[j]);
            *(float4*)&hs[lr * HP + cb]     = make_float4(v[0], v[1], v[2], v[3]);
            *(float4*)&hs[lr * HP + cb + 4] = make_float4(v[4], v[5], v[6], v[7]);
        }
    }
    __syncthreads();

    kloop_h(hs, Ws2, rg, cg, acc);
    {
        float bv[8];
#pragma unroll
        for (int j = 0; j < 8; j++) bv[j] = b2[cb + j];
#pragma unroll
        for (int i = 0; i < 4; i++) {
            int row = r0 + rg * 4 + i;
            if (row < nrows) {
                float4 a0 = *(const float4*)&A[row * FDIM + cb];
                float4 a1 = *(const float4*)&A[row * FDIM + cb + 4];
                float v[8];
#pragma unroll
                for (int j = 0; j < 8; j++) v[j] = acc[i][j] + bv[j];
                v[0] += a0.x; v[1] += a0.y; v[2] += a0.z; v[3] += a0.w;
                v[4] += a1.x; v[5] += a1.y; v[6] += a1.z; v[7] += a1.w;
                *(float4*)&C[row * FDIM + cb]     = make_float4(v[0], v[1], v[2], v[3]);
                *(float4*)&C[row * FDIM + cb + 4] = make_float4(v[4], v[5], v[6], v[7]);
            }
        }
    }
}

// ---------------- dW GEMM: C = uvec*base + act(A)@W + b ----------------
__global__ void __launch_bounds__(256) gemm_dw(
    const float* __restrict__ A, const float* __restrict__ W, const float* __restrict__ bias,
    const float* __restrict__ base, const float* __restrict__ uvec,
    float* __restrict__ C, int nrows) {
    extern __shared__ float sm[];
    float* Ws = sm;
    float* As = sm + 16384;
    const int tid = threadIdx.x;
    const int r0 = blockIdx.x * TR;
    load_W(W, Ws, tid);
    load_Atr<1>(A, As, tid, r0, nrows);
    __syncthreads();
    const int rg = tid >> 4, cg = tid & 15, cb = cg * 8;
    float acc[4][8];
    kloop128(As, Ws, rg, cg, acc);
    float bv[8], uv[8];
#pragma unroll
    for (int j = 0; j < 8; j++) { bv[j] = bias[cb + j]; uv[j] = uvec[cb + j]; }
#pragma unroll
    for (int i = 0; i < 4; i++) {
        int row = r0 + rg * 4 + i;
        if (row < nrows) {
            float4 x0 = *(const float4*)&base[row * FDIM + cb];
            float4 x1 = *(const float4*)&base[row * FDIM + cb + 4];
            float v[8];
#pragma unroll
            for (int j = 0; j < 8; j++) v[j] = acc[i][j] + bv[j];
            v[0] += uv[0] * x0.x; v[1] += uv[1] * x0.y; v[2] += uv[2] * x0.z; v[3] += uv[3] * x0.w;
            v[4] += uv[4] * x1.x; v[5] += uv[5] * x1.y; v[6] += uv[6] * x1.z; v[7] += uv[7] * x1.w;
            *(float4*)&C[row * FDIM + cb]     = make_float4(v[0], v[1], v[2], v[3]);
            *(float4*)&C[row * FDIM + cb + 4] = make_float4(v[4], v[5], v[6], v[7]);
        }
    }
}

// ---------------- init: x = embeddings[Z] ----------------
__global__ void init_kernel(const int* __restrict__ Z, const float* __restrict__ emb,
                            float* __restrict__ x) {
    int idx = blockIdx.x * blockDim.x + threadIdx.x;
    if (idx < NATOMS * FDIM) {
        int n = idx >> 7, f = idx & 127;
        x[idx] = emb[Z[n] * FDIM + f];
    }
}

// ---------------- pair: Dij + rbf ----------------
__global__ void pair_kernel(const float* __restrict__ R, const int* __restrict__ idx_i,
                            const int* __restrict__ idx_j, const float* __restrict__ cent,
                            const float* __restrict__ wid, float* __restrict__ rbf,
                            float* __restrict__ Dij_out) {
    int gid = blockIdx.x * blockDim.x + threadIdx.x;
    int p = gid >> 6, k = gid & 63;
    if (p >= NPAIRS) return;
    int i = idx_i[p], j = idx_j[p];
    float dx = R[i * 3 + 0] - R[j * 3 + 0];
    float dy = R[i * 3 + 1] - R[j * 3 + 1];
    float dz = R[i * 3 + 2] - R[j * 3 + 2];
    float D = sqrtf(fmaxf(dx * dx + dy * dy + dz * dz, 0.f));
    if (k == 0) Dij_out[p] = D;
    float xr = D * 0.1f;
    float cut = 0.f;
    if (xr < 1.f) {
        float x3 = xr * xr * xr, x4 = x3 * xr, x5 = x4 * xr;
        cut = 1.f - 6.f * x5 + 15.f * x4 - 10.f * x3;
    }
    float ed = __expf(-D);
    float t = ed - cent[k];
    rbf[p * KDIM + k] = cut * __expf(-wid[k] * t * t);
}

// ---------------- message: m[idx_i] += (rbf @ k2f) * xj[idx_j], 4 pairs/thread ----------------
__global__ void __launch_bounds__(256) message_kernel(
    const float* __restrict__ rbf, const float* __restrict__ k2f,
    const float* __restrict__ xj, const int* __restrict__ idx_i,
    const int* __restrict__ idx_j, float* __restrict__ m) {
    __shared__ float k2fs[KDIM * FDIM];   // 32 KB
    __shared__ float rbfs[32 * KDIM];     // 8 KB
    const int tid = threadIdx.x;
    {
        const float4* kv = (const float4*)k2f;
        float4* ksv = (float4*)k2fs;
#pragma unroll
        for (int i = 0; i < 8; i++) ksv[tid + i * 256] = kv[tid + i * 256];
    }
    const int fg = tid & 31;   // 32 feature groups of 4
    const int ps = tid >> 5;   // 8 pair-quad slots
    const int nch = (NPAIRS + 31) >> 5;   // 32 pairs per chunk
    for (int ch = blockIdx.x; ch < nch; ch += gridDim.x) {
        int base = ch * 32;
        __syncthreads();
        {
            float4* rv = (float4*)rbfs;
#pragma unroll
            for (int i = 0; i < 2; i++) {
                int v = tid + i * 256;        // float4 index into 32x64 tile
                int pp = base + (v >> 4);
                rv[v] = (pp < NPAIRS) ? ((const float4*)rbf)[pp * 16 + (v & 15)]
                                      : make_float4(0.f, 0.f, 0.f, 0.f);
            }
        }
        __syncthreads();
        int p0 = base + ps * 4;
        float4 g0 = make_float4(0,0,0,0), g1 = g0, g2 = g0, g3 = g0;
        const float* rr = &rbfs[ps * 4 * KDIM];
#pragma unroll 4
        for (int k = 0; k < KDIM; k++) {
            float4 w = *(const float4*)&k2fs[k * FDIM + fg * 4];
            float r0v = rr[0 * KDIM + k], r1v = rr[1 * KDIM + k];
            float r2v = rr[2 * KDIM + k], r3v = rr[3 * KDIM + k];
            g0.x = fmaf(r0v, w.x, g0.x); g0.y = fmaf(r0v, w.y, g0.y);
            g0.z = fmaf(r0v, w.z, g0.z); g0.w = fmaf(r0v, w.w, g0.w);
            g1.x = fmaf(r1v, w.x, g1.x); g1.y = fmaf(r1v, w.y, g1.y);
            g1.z = fmaf(r1v, w.z, g1.z); g1.w = fmaf(r1v, w.w, g1.w);
            g2.x = fmaf(r2v, w.x, g2.x); g2.y = fmaf(r2v, w.y, g2.y);
            g2.z = fmaf(r2v, w.z, g2.z); g2.w = fmaf(r2v, w.w, g2.w);
            g3.x = fmaf(r3v, w.x, g3.x); g3.y = fmaf(r3v, w.y, g3.y);
            g3.z = fmaf(r3v, w.z, g3.z); g3.w = fmaf(r3v, w.w, g3.w);
        }
        float4 gq[4] = {g0, g1, g2, g3};
#pragma unroll
        for (int q = 0; q < 4; q++) {
            int p = p0 + q;
            if (p < NPAIRS) {
                int i = idx_i[p], j = idx_j[p];
                float4 xv = *(const float4*)(xj + j * FDIM + fg * 4);
                red_add_f4(m + i * FDIM + fg * 4,
                           make_float4(gq[q].x * xv.x, gq[q].y * xv.y,
                                       gq[q].z * xv.z, gq[q].w * xv.w));
            }
        }
    }
}

// ---------------- output block ----------------
__global__ void outblock_kernel(const float* __restrict__ o, const float* __restrict__ ow,
                                float* __restrict__ Ea, float* __restrict__ Qa,
                                float* __restrict__ last2, float* __restrict__ nh, int bpos) {
    int n = blockIdx.x, tid = threadIdx.x;
    float a = actf(o[n * FDIM + tid]);
    float e = a * ow[tid * 2], q = a * ow[tid * 2 + 1];
#pragma unroll
    for (int s = 16; s; s >>= 1) {
        e += __shfl_xor_sync(0xffffffffu, e, s);
        q += __shfl_xor_sync(0xffffffffu, q, s);
    }
    __shared__ float se[4], sq[4];
    if ((tid & 31) == 0) { se[tid >> 5] = e; sq[tid >> 5] = q; }
    __syncthreads();
    if (tid == 0) {
        e = se[0] + se[1] + se[2] + se[3];
        q = sq[0] + sq[1] + sq[2] + sq[3];
        Ea[n] += e; Qa[n] += q;
        float e2 = e * e, q2 = q * q;
        if (bpos) {
            float le = last2[2 * n], lq = last2[2 * n + 1];
            atomicAdd(nh, e2 / (e2 + le + 1e-7f) + q2 / (q2 + lq + 1e-7f));
        }
        last2[2 * n] = e2; last2[2 * n + 1] = q2;
    }
}

// ---------------- final ----------------
__global__ void final_kernel(const int* __restrict__ Z, const float* __restrict__ Ea,
                             const float* __restrict__ Qa, const float* __restrict__ nh,
                             const float* __restrict__ Es, const float* __restrict__ Eh,
                             const float* __restrict__ Qs, const float* __restrict__ Qh,
                             float* __restrict__ out) {
    int n = blockIdx.x * blockDim.x + threadIdx.x;
    if (n < NATOMS) {
        int z = Z[n];
        out[n]          = Es[z] * Ea[n] + Eh[z];
        out[NATOMS + n] = Qs[z] * Qa[n] + Qh[z];
    }
    if (n == 0) out[2 * NATOMS + NPAIRS] = *nh / (2.f * NATOMS);
}

// ---------------- launch ----------------
extern "C" void kernel_launch(void* const* d_in, const int* in_sizes, int n_in,
                              void* d_out, int out_size) {
    const int*   Z      = (const int*)  d_in[0];
    const float* R      = (const float*)d_in[1];
    const int*   idx_i  = (const int*)  d_in[2];
    const int*   idx_j  = (const int*)  d_in[3];
    const float* emb    = (const float*)d_in[4];
    const float* cent   = (const float*)d_in[5];
    const float* wid    = (const float*)d_in[6];
    const float* k2f    = (const float*)d_in[7];
    const float* Wi     = (const float*)d_in[8];
    const float* bi     = (const float*)d_in[9];
    const float* Wj     = (const float*)d_in[10];
    const float* bj     = (const float*)d_in[11];
    const float* riW1   = (const float*)d_in[12];
    const float* rib1   = (const float*)d_in[13];
    const float* riW2   = (const float*)d_in[14];
    const float* rib2   = (const float*)d_in[15];
    const float* dW     = (const float*)d_in[16];
    const float* db     = (const float*)d_in[17];
    const float* u      = (const float*)d_in[18];
    const float* raW1   = (const float*)d_in[19];
    const float* rab1   = (const float*)d_in[20];
    const float* raW2   = (const float*)d_in[21];
    const float* rab2   = (const float*)d_in[22];
    const float* roW1   = (const float*)d_in[23];
    const float* rob1   = (const float*)d_in[24];
    const float* roW2   = (const float*)d_in[25];
    const float* rob2   = (const float*)d_in[26];
    const float* outW   = (const float*)d_in[27];
    const float* Escale = (const float*)d_in[28];
    const float* Eshift = (const float*)d_in[29];
    const float* Qscale = (const float*)d_in[30];
    const float* Qshift = (const float*)d_in[31];
    float* out = (float*)d_out;

    float *rbf, *x, *xjb, *m, *o, *Ea, *Qa, *l2, *nh;
    cudaGetSymbolAddress((void**)&rbf, g_rbf);
    cudaGetSymbolAddress((void**)&x,   g_x);
    cudaGetSymbolAddress((void**)&xjb, g_xj);
    cudaGetSymbolAddress((void**)&m,   g_m);
    cudaGetSymbolAddress((void**)&o,   g_o);
    cudaGetSymbolAddress((void**)&Ea,  g_Ea);
    cudaGetSymbolAddress((void**)&Qa,  g_Qa);
    cudaGetSymbolAddress((void**)&l2,  g_l2);
    cudaGetSymbolAddress((void**)&nh,  g_nh);

    cudaFuncSetAttribute(gemm_dual,  cudaFuncAttributeMaxDynamicSharedMemorySize, SM_DUAL);
    cudaFuncSetAttribute(gemm_resid, cudaFuncAttributeMaxDynamicSharedMemorySize, SM_RES);
    cudaFuncSetAttribute(gemm_dw,    cudaFuncAttributeMaxDynamicSharedMemorySize, SM_PLAIN);

    cudaMemsetAsync(Ea, 0, NATOMS * sizeof(float));
    cudaMemsetAsync(Qa, 0, NATOMS * sizeof(float));
    cudaMemsetAsync(nh, 0, sizeof(float));

    init_kernel<<<(NATOMS * FDIM + 255) / 256, 256>>>(Z, emb, x);
    pair_kernel<<<(NPAIRS * KDIM + 255) / 256, 256>>>(R, idx_i, idx_j, cent, wid, rbf,
                                                      out + 2 * NATOMS);

    const int GB = (NATOMS + TR - 1) / TR;  // 157
    for (int b = 0; b < NB; b++) {
        gemm_dual<<<GB, 256, SM_DUAL>>>(x, Wi + b * 16384, bi + b * 128,
                                        Wj + b * 16384, bj + b * 128, m, xjb, NATOMS);
        message_kernel<<<592, 256>>>(rbf, k2f + b * KDIM * FDIM, xjb, idx_i, idx_j, m);
        for (int l = 0; l < NRI; l++) {
            int w = b * NRI + l;
            gemm_resid<<<GB, 256, SM_RES>>>(m, riW1 + w * 16384, rib1 + w * 128,
                                            riW2 + w * 16384, rib2 + w * 128, m, NATOMS);
        }
        gemm_dw<<<GB, 256, SM_PLAIN>>>(m, dW + b * 16384, db + b * 128, x, u + b * 128, x, NATOMS);
        for (int l = 0; l < NRA; l++) {
            int w = b * NRA + l;
            gemm_resid<<<GB, 256, SM_RES>>>(x, raW1 + w * 16384, rab1 + w * 128,
                                            raW2 + w * 16384, rab2 + w * 128, x, NATOMS);
        }
        gemm_resid<<<GB, 256, SM_RES>>>(x, roW1 + b * 16384, rob1 + b * 128,
                                        roW2 + b * 16384, rob2 + b * 128, o, NATOMS);
        outblock_kernel<<<NATOMS, 128>>>(o, outW + b * FDIM * 2, Ea, Qa, l2, nh, b);
    }
    final_kernel<<<(NATOMS + 255) / 256, 256>>>(Z, Ea, Qa, nh, Escale, Eshift,
                                                Qscale, Qshift, out);
}

// round 6
// speedup vs baseline: 1.8988x; 1.5333x over previous
#include <cuda_runtime.h>
#include <cuda_bf16.h>
#include <cstdint>

#define NATOMS 10000
#define NPAIRS 320000
#define FDIM 128
#define KDIM 64
#define NB 5
#define NRI 3
#define NRA 2
#define NRO 1

// padded bf16 smem layout: row = 128 bf16 = 64 words + 4 pad words = 68 words (272 B)
#define PW 68
#define A_LO 4352            // A plane = 64 rows * 68 = 4352 words
#define WPLANE 8704          // W plane = 128 rows * 68 = 8704 words
#define MATW 17408           // one matrix = hi+lo planes
#define SM_RES  (43520 * 4)  // A(8704) + 2 matrices (34816)
#define SM_DUAL (43520 * 4)
#define SM_DW   (26112 * 4)  // A(8704) + 1 matrix (17408)

// ---------------- scratch ----------------
__device__ float g_rbf[NPAIRS * KDIM];
__device__ float g_x [NATOMS * FDIM];
__device__ float g_xj[NATOMS * FDIM];
__device__ float g_m [NATOMS * FDIM];
__device__ float g_o [NATOMS * FDIM];
__device__ float g_Ea[NATOMS];
__device__ float g_Qa[NATOMS];
__device__ float g_l2[NATOMS * 2];
__device__ float g_nh;
// 75 weight matrices in padded B-layout [n][k], hi plane then lo plane
__device__ uint32_t g_wbf[75 * MATW];

__device__ __forceinline__ float actf(float x) {
    return fmaxf(x, 0.f) + log1pf(__expf(-fabsf(x))) - 0.69314718055994531f;
}

__device__ __forceinline__ void red_add_f4(float* p, float4 v) {
    asm volatile("red.global.add.v4.f32 [%0], {%1,%2,%3,%4};"
                 :: "l"(p), "f"(v.x), "f"(v.y), "f"(v.z), "f"(v.w) : "memory");
}

__device__ __forceinline__ uint32_t pack_hi(float a, float b) {
    __nv_bfloat16 h0 = __float2bfloat16(a), h1 = __float2bfloat16(b);
    return (uint32_t)__bfloat16_as_ushort(h0) | ((uint32_t)__bfloat16_as_ushort(h1) << 16);
}
__device__ __forceinline__ uint32_t pack_lo(float a, float b) {
    __nv_bfloat16 h0 = __float2bfloat16(a), h1 = __float2bfloat16(b);
    float r0 = a - __bfloat162float(h0), r1 = b - __bfloat162float(h1);
    __nv_bfloat16 l0 = __float2bfloat16(r0), l1 = __float2bfloat16(r1);
    return (uint32_t)__bfloat16_as_ushort(l0) | ((uint32_t)__bfloat16_as_ushort(l1) << 16);
}

__device__ __forceinline__ void mma_bf16(float c[4], const uint32_t a[4], const uint32_t b[2]) {
    asm volatile(
        "mma.sync.aligned.m16n8k16.row.col.f32.bf16.bf16.f32 "
        "{%0,%1,%2,%3}, {%4,%5,%6,%7}, {%8,%9}, {%0,%1,%2,%3};"
        : "+f"(c[0]), "+f"(c[1]), "+f"(c[2]), "+f"(c[3])
        : "r"(a[0]), "r"(a[1]), "r"(a[2]), "r"(a[3]), "r"(b[0]), "r"(b[1]));
}

// ---- A tile: fp32 gmem -> (act) -> bf16 hi/lo padded planes (64 rows x 128 k) ----
template <int PRE>
__device__ __forceinline__ void conv_A(const float* __restrict__ A, uint32_t* sm,
                                       int tid, int r0, int nrows) {
#pragma unroll 4
    for (int i = 0; i < 16; i++) {
        int v = tid + i * 256;          // 4096 word-pairs
        int row = v >> 6, kp = v & 63;
        float2 av = make_float2(0.f, 0.f);
        if (r0 + row < nrows) av = *(const float2*)(A + (size_t)(r0 + row) * FDIM + kp * 2);
        if (PRE) { av.x = actf(av.x); av.y = actf(av.y); }
        sm[row * PW + kp]        = pack_hi(av.x, av.y);
        sm[A_LO + row * PW + kp] = pack_lo(av.x, av.y);
    }
}

// ---- copy one full weight matrix (hi+lo planes, 69632 B) gmem->smem ----
__device__ __forceinline__ void copy_mat(const uint32_t* __restrict__ g, uint32_t* s, int tid) {
    const uint4* gv = (const uint4*)g;
    uint4* sv = (uint4*)s;
#pragma unroll
    for (int i = 0; i < 17; i++) sv[tid + i * 256] = gv[tid + i * 256];   // 17*256=4352 uint4
}

// ---- warp k-loop: acc += act(A) @ W  (bf16 hi/lo 3-combo), warp tile 32x32 ----
__device__ __forceinline__ void kloop(const uint32_t* __restrict__ sm, int woff,
                                      int wr0, int wc0, int lane, float acc[2][4][4]) {
    const int g = lane >> 2, tig = lane & 3;
#pragma unroll
    for (int ks = 0; ks < 8; ks++) {
        const int kw = ks * 8 + tig;
        uint32_t ah[2][4], al[2][4];
#pragma unroll
        for (int mg = 0; mg < 2; mg++) {
            int b = (wr0 + mg * 16 + g) * PW + kw;
            ah[mg][0] = sm[b];            ah[mg][1] = sm[b + 8 * PW];
            ah[mg][2] = sm[b + 4];        ah[mg][3] = sm[b + 8 * PW + 4];
            al[mg][0] = sm[A_LO + b];     al[mg][1] = sm[A_LO + b + 8 * PW];
            al[mg][2] = sm[A_LO + b + 4]; al[mg][3] = sm[A_LO + b + 8 * PW + 4];
        }
#pragma unroll
        for (int ng = 0; ng < 4; ng++) {
            int nb = woff + (wc0 + ng * 8 + g) * PW + kw;
            uint32_t bh[2] = { sm[nb],          sm[nb + 4] };
            uint32_t bl[2] = { sm[nb + WPLANE], sm[nb + WPLANE + 4] };
#pragma unroll
            for (int mg = 0; mg < 2; mg++) {
                mma_bf16(acc[mg][ng], ah[mg], bh);
                mma_bf16(acc[mg][ng], ah[mg], bl);
                mma_bf16(acc[mg][ng], al[mg], bh);
            }
        }
    }
}

__device__ __forceinline__ void zero_acc(float acc[2][4][4]) {
#pragma unroll
    for (int a = 0; a < 2; a++)
#pragma unroll
        for (int b = 0; b < 4; b++)
#pragma unroll
            for (int c = 0; c < 4; c++) acc[a][b][c] = 0.f;
}

// ---- dual: C1 = act(act(A)@W1+b1), C2 = act(act(A)@W2+b2) ----
__global__ void __launch_bounds__(256, 1) gemm_dual_mma(
    const float* __restrict__ A, const uint32_t* __restrict__ w1,
    const uint32_t* __restrict__ w2, const float* __restrict__ b1,
    const float* __restrict__ b2, float* __restrict__ C1, float* __restrict__ C2, int nrows) {
    extern __shared__ uint32_t sm[];
    const int tid = threadIdx.x, lane = tid & 31, wid = tid >> 5;
    const int wr0 = (wid >> 2) * 32, wc0 = (wid & 3) * 32;
    const int r0 = blockIdx.x * 64;
    const int g = lane >> 2, tig = lane & 3;

    conv_A<1>(A, sm, tid, r0, nrows);
    copy_mat(w1, sm + 8704, tid);
    copy_mat(w2, sm + 26112, tid);
    __syncthreads();

    float acc[2][4][4];
#pragma unroll
    for (int ph = 0; ph < 2; ph++) {
        zero_acc(acc);
        kloop(sm, ph ? 26112 : 8704, wr0, wc0, lane, acc);
        const float* bb = ph ? b2 : b1;
        float* CC = ph ? C2 : C1;
#pragma unroll
        for (int mg = 0; mg < 2; mg++) {
            int ra = r0 + wr0 + mg * 16 + g, rb = ra + 8;
#pragma unroll
            for (int ng = 0; ng < 4; ng++) {
                int col = wc0 + ng * 8 + 2 * tig;
                float bv0 = bb[col], bv1 = bb[col + 1];
                if (ra < nrows)
                    *(float2*)(CC + (size_t)ra * FDIM + col) =
                        make_float2(actf(acc[mg][ng][0] + bv0), actf(acc[mg][ng][1] + bv1));
                if (rb < nrows)
                    *(float2*)(CC + (size_t)rb * FDIM + col) =
                        make_float2(actf(acc[mg][ng][2] + bv0), actf(acc[mg][ng][3] + bv1));
            }
        }
    }
}

// ---- resid: C = A + act(act(A)@W1+b1)@W2 + b2 ----
__global__ void __launch_bounds__(256, 1) gemm_resid_mma(
    const float* __restrict__ A, const uint32_t* __restrict__ w1,
    const uint32_t* __restrict__ w2, const float* __restrict__ b1,
    const float* __restrict__ b2, float* __restrict__ C, int nrows) {
    extern __shared__ uint32_t sm[];
    const int tid = threadIdx.x, lane = tid & 31, wid = tid >> 5;
    const int wr0 = (wid >> 2) * 32, wc0 = (wid & 3) * 32;
    const int r0 = blockIdx.x * 64;
    const int g = lane >> 2, tig = lane & 3;

    conv_A<1>(A, sm, tid, r0, nrows);
    copy_mat(w1, sm + 8704, tid);
    copy_mat(w2, sm + 26112, tid);
    __syncthreads();

    float acc[2][4][4];
    zero_acc(acc);
    kloop(sm, 8704, wr0, wc0, lane, acc);
    __syncthreads();                     // all reads of A planes done

    // h = act(. + b1) -> back into A hi/lo planes
#pragma unroll
    for (int mg = 0; mg < 2; mg++) {
        int ra = wr0 + mg * 16 + g, rb = ra + 8;
#pragma unroll
        for (int ng = 0; ng < 4; ng++) {
            int col = wc0 + ng * 8 + 2 * tig;
            float bv0 = b1[col], bv1 = b1[col + 1];
            float h0 = actf(acc[mg][ng][0] + bv0), h1 = actf(acc[mg][ng][1] + bv1);
            float h2 = actf(acc[mg][ng][2] + bv0), h3 = actf(acc[mg][ng][3] + bv1);
            int wa = ra * PW + col / 2, wb = rb * PW + col / 2;
            sm[wa] = pack_hi(h0, h1); sm[A_LO + wa] = pack_lo(h0, h1);
            sm[wb] = pack_hi(h2, h3); sm[A_LO + wb] = pack_lo(h2, h3);
        }
    }
    __syncthreads();

    zero_acc(acc);
    kloop(sm, 26112, wr0, wc0, lane, acc);

#pragma unroll
    for (int mg = 0; mg < 2; mg++) {
        int ra = r0 + wr0 + mg * 16 + g, rb = ra + 8;
#pragma unroll
        for (int ng = 0; ng < 4; ng++) {
            int col = wc0 + ng * 8 + 2 * tig;
            float bv0 = b2[col], bv1 = b2[col + 1];
            if (ra < nrows) {
                float2 a = *(const float2*)(A + (size_t)ra * FDIM + col);
                *(float2*)(C + (size_t)ra * FDIM + col) =
                    make_float2(a.x + acc[mg][ng][0] + bv0, a.y + acc[mg][ng][1] + bv1);
            }
            if (rb < nrows) {
                float2 a = *(const float2*)(A + (size_t)rb * FDIM + col);
                *(float2*)(C + (size_t)rb * FDIM + col) =
                    make_float2(a.x + acc[mg][ng][2] + bv0, a.y + acc[mg][ng][3] + bv1);
            }
        }
    }
}

// ---- dw: C = uvec*base + act(A)@W + bias ----
__global__ void __launch_bounds__(256, 1) gemm_dw_mma(
    const float* __restrict__ A, const uint32_t* __restrict__ w,
    const float* __restrict__ bias, const float* __restrict__ base,
    const float* __restrict__ uvec, float* __restrict__ C, int nrows) {
    extern __shared__ uint32_t sm[];
    const int tid = threadIdx.x, lane = tid & 31, wid = tid >> 5;
    const int wr0 = (wid >> 2) * 32, wc0 = (wid & 3) * 32;
    const int r0 = blockIdx.x * 64;
    const int g = lane >> 2, tig = lane & 3;

    conv_A<1>(A, sm, tid, r0, nrows);
    copy_mat(w, sm + 8704, tid);
    __syncthreads();

    float acc[2][4][4];
    zero_acc(acc);
    kloop(sm, 8704, wr0, wc0, lane, acc);

#pragma unroll
    for (int mg = 0; mg < 2; mg++) {
        int ra = r0 + wr0 + mg * 16 + g, rb = ra + 8;
#pragma unroll
        for (int ng = 0; ng < 4; ng++) {
            int col = wc0 + ng * 8 + 2 * tig;
            float bv0 = bias[col], bv1 = bias[col + 1];
            float u0 = uvec[col], u1 = uvec[col + 1];
            if (ra < nrows) {
                float2 x = *(const float2*)(base + (size_t)ra * FDIM + col);
                *(float2*)(C + (size_t)ra * FDIM + col) =
                    make_float2(u0 * x.x + acc[mg][ng][0] + bv0, u1 * x.y + acc[mg][ng][1] + bv1);
            }
            if (rb < nrows) {
                float2 x = *(const float2*)(base + (size_t)rb * FDIM + col);
                *(float2*)(C + (size_t)rb * FDIM + col) =
                    make_float2(u0 * x.x + acc[mg][ng][2] + bv0, u1 * x.y + acc[mg][ng][3] + bv1);
            }
        }
    }
}

// ---- precompute: fp32 weights W[k][n] -> padded bf16 hi/lo planes [n][k] ----
__global__ void conv_weights(const float* __restrict__ src, uint32_t* __restrict__ dst,
                             int nmat) {
    int gid = blockIdx.x * blockDim.x + threadIdx.x;
    if (gid >= nmat * 16384) return;
    int m = gid >> 14, e = gid & 16383;
    int k = e >> 7, n = e & 127;
    float x = src[gid];
    __nv_bfloat16 hi = __float2bfloat16(x);
    __nv_bfloat16 lo = __float2bfloat16(x - __bfloat162float(hi));
    char* bp = (char*)(dst + (size_t)m * MATW);
    *(__nv_bfloat16*)(bp + n * 272 + k * 2)         = hi;
    *(__nv_bfloat16*)(bp + 34816 + n * 272 + k * 2) = lo;
}

// ---------------- init: x = embeddings[Z] ----------------
__global__ void init_kernel(const int* __restrict__ Z, const float* __restrict__ emb,
                            float* __restrict__ x) {
    int idx = blockIdx.x * blockDim.x + threadIdx.x;
    if (idx < NATOMS * FDIM) {
        int n = idx >> 7, f = idx & 127;
        x[idx] = emb[Z[n] * FDIM + f];
    }
}

// ---------------- pair: Dij + rbf ----------------
__global__ void pair_kernel(const float* __restrict__ R, const int* __restrict__ idx_i,
                            const int* __restrict__ idx_j, const float* __restrict__ cent,
                            const float* __restrict__ wid, float* __restrict__ rbf,
                            float* __restrict__ Dij_out) {
    int gid = blockIdx.x * blockDim.x + threadIdx.x;
    int p = gid >> 6, k = gid & 63;
    if (p >= NPAIRS) return;
    int i = idx_i[p], j = idx_j[p];
    float dx = R[i * 3 + 0] - R[j * 3 + 0];
    float dy = R[i * 3 + 1] - R[j * 3 + 1];
    float dz = R[i * 3 + 2] - R[j * 3 + 2];
    float D = sqrtf(fmaxf(dx * dx + dy * dy + dz * dz, 0.f));
    if (k == 0) Dij_out[p] = D;
    float xr = D * 0.1f;
    float cut = 0.f;
    if (xr < 1.f) {
        float x3 = xr * xr * xr, x4 = x3 * xr, x5 = x4 * xr;
        cut = 1.f - 6.f * x5 + 15.f * x4 - 10.f * x3;
    }
    float ed = __expf(-D);
    float t = ed - cent[k];
    rbf[p * KDIM + k] = cut * __expf(-wid[k] * t * t);
}

// ---------------- message: m[idx_i] += (rbf @ k2f) * xj[idx_j], 4 pairs/thread ----------------
__global__ void __launch_bounds__(256) message_kernel(
    const float* __restrict__ rbf, const float* __restrict__ k2f,
    const float* __restrict__ xj, const int* __restrict__ idx_i,
    const int* __restrict__ idx_j, float* __restrict__ m) {
    __shared__ float k2fs[KDIM * FDIM];
    __shared__ float rbfs[32 * KDIM];
    const int tid = threadIdx.x;
    {
        const float4* kv = (const float4*)k2f;
        float4* ksv = (float4*)k2fs;
#pragma unroll
        for (int i = 0; i < 8; i++) ksv[tid + i * 256] = kv[tid + i * 256];
    }
    const int fg = tid & 31;
    const int ps = tid >> 5;
    const int nch = (NPAIRS + 31) >> 5;
    for (int ch = blockIdx.x; ch < nch; ch += gridDim.x) {
        int base = ch * 32;
        __syncthreads();
        {
            float4* rv = (float4*)rbfs;
#pragma unroll
            for (int i = 0; i < 2; i++) {
                int v = tid + i * 256;
                int pp = base + (v >> 4);
                rv[v] = (pp < NPAIRS) ? ((const float4*)rbf)[pp * 16 + (v & 15)]
                                      : make_float4(0.f, 0.f, 0.f, 0.f);
            }
        }
        __syncthreads();
        int p0 = base + ps * 4;
        float4 g0 = make_float4(0,0,0,0), g1 = g0, g2 = g0, g3 = g0;
        const float* rr = &rbfs[ps * 4 * KDIM];
#pragma unroll 4
        for (int k = 0; k < KDIM; k++) {
            float4 w = *(const float4*)&k2fs[k * FDIM + fg * 4];
            float r0v = rr[0 * KDIM + k], r1v = rr[1 * KDIM + k];
            float r2v = rr[2 * KDIM + k], r3v = rr[3 * KDIM + k];
            g0.x = fmaf(r0v, w.x, g0.x); g0.y = fmaf(r0v, w.y, g0.y);
            g0.z = fmaf(r0v, w.z, g0.z); g0.w = fmaf(r0v, w.w, g0.w);
            g1.x = fmaf(r1v, w.x, g1.x); g1.y = fmaf(r1v, w.y, g1.y);
            g1.z = fmaf(r1v, w.z, g1.z); g1.w = fmaf(r1v, w.w, g1.w);
            g2.x = fmaf(r2v, w.x, g2.x); g2.y = fmaf(r2v, w.y, g2.y);
            g2.z = fmaf(r2v, w.z, g2.z); g2.w = fmaf(r2v, w.w, g2.w);
            g3.x = fmaf(r3v, w.x, g3.x); g3.y = fmaf(r3v, w.y, g3.y);
            g3.z = fmaf(r3v, w.z, g3.z); g3.w = fmaf(r3v, w.w, g3.w);
        }
        float4 gq[4] = {g0, g1, g2, g3};
#pragma unroll
        for (int q = 0; q < 4; q++) {
            int p = p0 + q;
            if (p < NPAIRS) {
                int i = idx_i[p], j = idx_j[p];
                float4 xv = *(const float4*)(xj + j * FDIM + fg * 4);
                red_add_f4(m + i * FDIM + fg * 4,
                           make_float4(gq[q].x * xv.x, gq[q].y * xv.y,
                                       gq[q].z * xv.z, gq[q].w * xv.w));
            }
        }
    }
}

// ---------------- output block ----------------
__global__ void outblock_kernel(const float* __restrict__ o, const float* __restrict__ ow,
                                float* __restrict__ Ea, float* __restrict__ Qa,
                                float* __restrict__ last2, float* __restrict__ nh, int bpos) {
    int n = blockIdx.x, tid = threadIdx.x;
    float a = actf(o[n * FDIM + tid]);
    float e = a * ow[tid * 2], q = a * ow[tid * 2 + 1];
#pragma unroll
    for (int s = 16; s; s >>= 1) {
        e += __shfl_xor_sync(0xffffffffu, e, s);
        q += __shfl_xor_sync(0xffffffffu, q, s);
    }
    __shared__ float se[4], sq[4];
    if ((tid & 31) == 0) { se[tid >> 5] = e; sq[tid >> 5] = q; }
    __syncthreads();
    if (tid == 0) {
        e = se[0] + se[1] + se[2] + se[3];
        q = sq[0] + sq[1] + sq[2] + sq[3];
        Ea[n] += e; Qa[n] += q;
        float e2 = e * e, q2 = q * q;
        if (bpos) {
            float le = last2[2 * n], lq = last2[2 * n + 1];
            atomicAdd(nh, e2 / (e2 + le + 1e-7f) + q2 / (q2 + lq + 1e-7f));
        }
        last2[2 * n] = e2; last2[2 * n + 1] = q2;
    }
}

// ---------------- final ----------------
__global__ void final_kernel(const int* __restrict__ Z, const float* __restrict__ Ea,
                             const float* __restrict__ Qa, const float* __restrict__ nh,
                             const float* __restrict__ Es, const float* __restrict__ Eh,
                             const float* __restrict__ Qs, const float* __restrict__ Qh,
                             float* __restrict__ out) {
    int n = blockIdx.x * blockDim.x + threadIdx.x;
    if (n < NATOMS) {
        int z = Z[n];
        out[n]          = Es[z] * Ea[n] + Eh[z];
        out[NATOMS + n] = Qs[z] * Qa[n] + Qh[z];
    }
    if (n == 0) out[2 * NATOMS + NPAIRS] = *nh / (2.f * NATOMS);
}

// ---------------- launch ----------------
extern "C" void kernel_launch(void* const* d_in, const int* in_sizes, int n_in,
                              void* d_out, int out_size) {
    const int*   Z      = (const int*)  d_in[0];
    const float* R      = (const float*)d_in[1];
    const int*   idx_i  = (const int*)  d_in[2];
    const int*   idx_j  = (const int*)  d_in[3];
    const float* emb    = (const float*)d_in[4];
    const float* cent   = (const float*)d_in[5];
    const float* wid    = (const float*)d_in[6];
    const float* k2f    = (const float*)d_in[7];
    const float* Wi     = (const float*)d_in[8];
    const float* bi     = (const float*)d_in[9];
    const float* Wj     = (const float*)d_in[10];
    const float* bj     = (const float*)d_in[11];
    const float* riW1   = (const float*)d_in[12];
    const float* rib1   = (const float*)d_in[13];
    const float* riW2   = (const float*)d_in[14];
    const float* rib2   = (const float*)d_in[15];
    const float* dW     = (const float*)d_in[16];
    const float* db     = (const float*)d_in[17];
    const float* u      = (const float*)d_in[18];
    const float* raW1   = (const float*)d_in[19];
    const float* rab1   = (const float*)d_in[20];
    const float* raW2   = (const float*)d_in[21];
    const float* rab2   = (const float*)d_in[22];
    const float* roW1   = (const float*)d_in[23];
    const float* rob1   = (const float*)d_in[24];
    const float* roW2   = (const float*)d_in[25];
    const float* rob2   = (const float*)d_in[26];
    const float* outW   = (const float*)d_in[27];
    const float* Escale = (const float*)d_in[28];
    const float* Eshift = (const float*)d_in[29];
    const float* Qscale = (const float*)d_in[30];
    const float* Qshift = (const float*)d_in[31];
    float* out = (float*)d_out;

    float *rbf, *x, *xjb, *m, *o, *Ea, *Qa, *l2, *nh;
    uint32_t* wbf;
    cudaGetSymbolAddress((void**)&rbf, g_rbf);
    cudaGetSymbolAddress((void**)&x,   g_x);
    cudaGetSymbolAddress((void**)&xjb, g_xj);
    cudaGetSymbolAddress((void**)&m,   g_m);
    cudaGetSymbolAddress((void**)&o,   g_o);
    cudaGetSymbolAddress((void**)&Ea,  g_Ea);
    cudaGetSymbolAddress((void**)&Qa,  g_Qa);
    cudaGetSymbolAddress((void**)&l2,  g_l2);
    cudaGetSymbolAddress((void**)&nh,  g_nh);
    cudaGetSymbolAddress((void**)&wbf, g_wbf);

    cudaFuncSetAttribute(gemm_dual_mma,  cudaFuncAttributeMaxDynamicSharedMemorySize, SM_DUAL);
    cudaFuncSetAttribute(gemm_resid_mma, cudaFuncAttributeMaxDynamicSharedMemorySize, SM_RES);
    cudaFuncSetAttribute(gemm_dw_mma,    cudaFuncAttributeMaxDynamicSharedMemorySize, SM_DW);

    cudaMemsetAsync(Ea, 0, NATOMS * sizeof(float));
    cudaMemsetAsync(Qa, 0, NATOMS * sizeof(float));
    cudaMemsetAsync(nh, 0, sizeof(float));

    // weight slots: Wi:0..4  Wj:5..9  riW1:10..24  riW2:25..39  dW:40..44
    // raW1:45..54  raW2:55..64  roW1:65..69  roW2:70..74
    auto cw = [&](const float* src, int slot0, int nmat) {
        conv_weights<<<(nmat * 16384 + 255) / 256, 256>>>(src, wbf + (size_t)slot0 * MATW, nmat);
    };
    cw(Wi, 0, NB); cw(Wj, 5, NB);
    cw(riW1, 10, NB * NRI); cw(riW2, 25, NB * NRI);
    cw(dW, 40, NB);
    cw(raW1, 45, NB * NRA); cw(raW2, 55, NB * NRA);
    cw(roW1, 65, NB); cw(roW2, 70, NB);

    init_kernel<<<(NATOMS * FDIM + 255) / 256, 256>>>(Z, emb, x);
    pair_kernel<<<(NPAIRS * KDIM + 255) / 256, 256>>>(R, idx_i, idx_j, cent, wid, rbf,
                                                      out + 2 * NATOMS);

    const int GB = (NATOMS + 63) / 64;  // 157
    auto WS = [&](int s) { return (const uint32_t*)(wbf + (size_t)s * MATW); };

    for (int b = 0; b < NB; b++) {
        gemm_dual_mma<<<GB, 256, SM_DUAL>>>(x, WS(0 + b), WS(5 + b),
                                            bi + b * 128, bj + b * 128, m, xjb, NATOMS);
        message_kernel<<<592, 256>>>(rbf, k2f + b * KDIM * FDIM, xjb, idx_i, idx_j, m);
        for (int l = 0; l < NRI; l++) {
            int wdx = b * NRI + l;
            gemm_resid_mma<<<GB, 256, SM_RES>>>(m, WS(10 + wdx), WS(25 + wdx),
                                                rib1 + wdx * 128, rib2 + wdx * 128, m, NATOMS);
        }
        gemm_dw_mma<<<GB, 256, SM_DW>>>(m, WS(40 + b), db + b * 128, x, u + b * 128, x, NATOMS);
        for (int l = 0; l < NRA; l++) {
            int wdx = b * NRA + l;
            gemm_resid_mma<<<GB, 256, SM_RES>>>(x, WS(45 + wdx), WS(55 + wdx),
                                                rab1 + wdx * 128, rab2 + wdx * 128, x, NATOMS);
        }
        gemm_resid_mma<<<GB, 256, SM_RES>>>(x, WS(65 + b), WS(70 + b),
                                            rob1 + b * 128, rob2 + b * 128, o, NATOMS);
        outblock_kernel<<<NATOMS, 128>>>(o, outW + b * FDIM * 2, Ea, Qa, l2, nh, b);
    }
    final_kernel<<<(NATOMS + 255) / 256, 256>>>(Z, Ea, Qa, nh, Escale, Eshift,
                                                Qscale, Qshift, out);
}

// round 7
// speedup vs baseline: 2.3086x; 1.2158x over previous
#include <cuda_runtime.h>
#include <cuda_bf16.h>
#include <cstdint>

#define NATOMS 10000
#define NPAIRS 320000
#define FDIM 128
#define KDIM 64
#define NB 5
#define NRI 3
#define NRA 2
#define NRO 1

// ---- dense GEMM smem layout (bf16 padded rows: 128 bf16 = 64 words + 4 pad) ----
#define PW 68
#define A_LO 4352
#define WPLANE 8704
#define MATW 17408
#define SM_RES  (43520 * 4)
#define SM_DUAL (43520 * 4)
#define SM_DW   (26112 * 4)

// ---- message MMA smem layout (K=64: rows = 32 words + 4 pad = 36) ----
#define MPW 36
#define OFF_K2FH 0
#define OFF_K2FL 4608
#define OFF_RBFH 9216
#define OFF_RBFL 11520
#define OFF_G    13824
#define SM_MSG  ((13824 + 8448) * 4)   // 89088 B
#define NCH     (NPAIRS / 64)          // 5000 chunks of 64 pairs

// ---------------- scratch ----------------
__device__ uint32_t g_rbfh[NPAIRS * 32];   // rbf hi plane, 2 bf16 per word
__device__ uint32_t g_rbfl[NPAIRS * 32];   // rbf lo plane
__device__ uint32_t g_k2fb[5 * 9216];      // k2f bf16 hi/lo padded planes
__device__ float g_x [NATOMS * FDIM];
__device__ float g_xj[NATOMS * FDIM];
__device__ float g_m [NATOMS * FDIM];
__device__ float g_o [NATOMS * FDIM];
__device__ float g_Ea[NATOMS];
__device__ float g_Qa[NATOMS];
__device__ float g_l2[NATOMS * 2];
__device__ float g_nh;
__device__ uint32_t g_wbf[75 * MATW];

__device__ __forceinline__ float actf(float x) {
    return fmaxf(x, 0.f) + log1pf(__expf(-fabsf(x))) - 0.69314718055994531f;
}

__device__ __forceinline__ void red_add_f4(float* p, float4 v) {
    asm volatile("red.global.add.v4.f32 [%0], {%1,%2,%3,%4};"
                 :: "l"(p), "f"(v.x), "f"(v.y), "f"(v.z), "f"(v.w) : "memory");
}

__device__ __forceinline__ uint32_t pack_hi(float a, float b) {
    __nv_bfloat16 h0 = __float2bfloat16(a), h1 = __float2bfloat16(b);
    return (uint32_t)__bfloat16_as_ushort(h0) | ((uint32_t)__bfloat16_as_ushort(h1) << 16);
}
__device__ __forceinline__ uint32_t pack_lo(float a, float b) {
    __nv_bfloat16 h0 = __float2bfloat16(a), h1 = __float2bfloat16(b);
    float r0 = a - __bfloat162float(h0), r1 = b - __bfloat162float(h1);
    __nv_bfloat16 l0 = __float2bfloat16(r0), l1 = __float2bfloat16(r1);
    return (uint32_t)__bfloat16_as_ushort(l0) | ((uint32_t)__bfloat16_as_ushort(l1) << 16);
}

__device__ __forceinline__ void mma_bf16(float c[4], const uint32_t a[4], const uint32_t b[2]) {
    asm volatile(
        "mma.sync.aligned.m16n8k16.row.col.f32.bf16.bf16.f32 "
        "{%0,%1,%2,%3}, {%4,%5,%6,%7}, {%8,%9}, {%0,%1,%2,%3};"
        : "+f"(c[0]), "+f"(c[1]), "+f"(c[2]), "+f"(c[3])
        : "r"(a[0]), "r"(a[1]), "r"(a[2]), "r"(a[3]), "r"(b[0]), "r"(b[1]));
}

// ================== dense GEMM machinery (unchanged from R6) ==================
template <int PRE>
__device__ __forceinline__ void conv_A(const float* __restrict__ A, uint32_t* sm,
                                       int tid, int r0, int nrows) {
#pragma unroll 4
    for (int i = 0; i < 16; i++) {
        int v = tid + i * 256;
        int row = v >> 6, kp = v & 63;
        float2 av = make_float2(0.f, 0.f);
        if (r0 + row < nrows) av = *(const float2*)(A + (size_t)(r0 + row) * FDIM + kp * 2);
        if (PRE) { av.x = actf(av.x); av.y = actf(av.y); }
        sm[row * PW + kp]        = pack_hi(av.x, av.y);
        sm[A_LO + row * PW + kp] = pack_lo(av.x, av.y);
    }
}

__device__ __forceinline__ void copy_mat(const uint32_t* __restrict__ g, uint32_t* s, int tid) {
    const uint4* gv = (const uint4*)g;
    uint4* sv = (uint4*)s;
#pragma unroll
    for (int i = 0; i < 17; i++) sv[tid + i * 256] = gv[tid + i * 256];
}

__device__ __forceinline__ void kloop(const uint32_t* __restrict__ sm, int woff,
                                      int wr0, int wc0, int lane, float acc[2][4][4]) {
    const int g = lane >> 2, tig = lane & 3;
#pragma unroll
    for (int ks = 0; ks < 8; ks++) {
        const int kw = ks * 8 + tig;
        uint32_t ah[2][4], al[2][4];
#pragma unroll
        for (int mg = 0; mg < 2; mg++) {
            int b = (wr0 + mg * 16 + g) * PW + kw;
            ah[mg][0] = sm[b];            ah[mg][1] = sm[b + 8 * PW];
            ah[mg][2] = sm[b + 4];        ah[mg][3] = sm[b + 8 * PW + 4];
            al[mg][0] = sm[A_LO + b];     al[mg][1] = sm[A_LO + b + 8 * PW];
            al[mg][2] = sm[A_LO + b + 4]; al[mg][3] = sm[A_LO + b + 8 * PW + 4];
        }
#pragma unroll
        for (int ng = 0; ng < 4; ng++) {
            int nb = woff + (wc0 + ng * 8 + g) * PW + kw;
            uint32_t bh[2] = { sm[nb],          sm[nb + 4] };
            uint32_t bl[2] = { sm[nb + WPLANE], sm[nb + WPLANE + 4] };
#pragma unroll
            for (int mg = 0; mg < 2; mg++) {
                mma_bf16(acc[mg][ng], ah[mg], bh);
                mma_bf16(acc[mg][ng], ah[mg], bl);
                mma_bf16(acc[mg][ng], al[mg], bh);
            }
        }
    }
}

__device__ __forceinline__ void zero_acc(float acc[2][4][4]) {
#pragma unroll
    for (int a = 0; a < 2; a++)
#pragma unroll
        for (int b = 0; b < 4; b++)
#pragma unroll
            for (int c = 0; c < 4; c++) acc[a][b][c] = 0.f;
}

__global__ void __launch_bounds__(256, 1) gemm_dual_mma(
    const float* __restrict__ A, const uint32_t* __restrict__ w1,
    const uint32_t* __restrict__ w2, const float* __restrict__ b1,
    const float* __restrict__ b2, float* __restrict__ C1, float* __restrict__ C2, int nrows) {
    extern __shared__ uint32_t sm[];
    const int tid = threadIdx.x, lane = tid & 31, wid = tid >> 5;
    const int wr0 = (wid >> 2) * 32, wc0 = (wid & 3) * 32;
    const int r0 = blockIdx.x * 64;
    const int g = lane >> 2, tig = lane & 3;

    conv_A<1>(A, sm, tid, r0, nrows);
    copy_mat(w1, sm + 8704, tid);
    copy_mat(w2, sm + 26112, tid);
    __syncthreads();

    float acc[2][4][4];
#pragma unroll
    for (int ph = 0; ph < 2; ph++) {
        zero_acc(acc);
        kloop(sm, ph ? 26112 : 8704, wr0, wc0, lane, acc);
        const float* bb = ph ? b2 : b1;
        float* CC = ph ? C2 : C1;
#pragma unroll
        for (int mg = 0; mg < 2; mg++) {
            int ra = r0 + wr0 + mg * 16 + g, rb = ra + 8;
#pragma unroll
            for (int ng = 0; ng < 4; ng++) {
                int col = wc0 + ng * 8 + 2 * tig;
                float bv0 = bb[col], bv1 = bb[col + 1];
                if (ra < nrows)
                    *(float2*)(CC + (size_t)ra * FDIM + col) =
                        make_float2(actf(acc[mg][ng][0] + bv0), actf(acc[mg][ng][1] + bv1));
                if (rb < nrows)
                    *(float2*)(CC + (size_t)rb * FDIM + col) =
                        make_float2(actf(acc[mg][ng][2] + bv0), actf(acc[mg][ng][3] + bv1));
            }
        }
    }
}

__global__ void __launch_bounds__(256, 1) gemm_resid_mma(
    const float* __restrict__ A, const uint32_t* __restrict__ w1,
    const uint32_t* __restrict__ w2, const float* __restrict__ b1,
    const float* __restrict__ b2, float* __restrict__ C, int nrows) {
    extern __shared__ uint32_t sm[];
    const int tid = threadIdx.x, lane = tid & 31, wid = tid >> 5;
    const int wr0 = (wid >> 2) * 32, wc0 = (wid & 3) * 32;
    const int r0 = blockIdx.x * 64;
    const int g = lane >> 2, tig = lane & 3;

    conv_A<1>(A, sm, tid, r0, nrows);
    copy_mat(w1, sm + 8704, tid);
    copy_mat(w2, sm + 26112, tid);
    __syncthreads();

    float acc[2][4][4];
    zero_acc(acc);
    kloop(sm, 8704, wr0, wc0, lane, acc);
    __syncthreads();

#pragma unroll
    for (int mg = 0; mg < 2; mg++) {
        int ra = wr0 + mg * 16 + g, rb = ra + 8;
#pragma unroll
        for (int ng = 0; ng < 4; ng++) {
            int col = wc0 + ng * 8 + 2 * tig;
            float bv0 = b1[col], bv1 = b1[col + 1];
            float h0 = actf(acc[mg][ng][0] + bv0), h1 = actf(acc[mg][ng][1] + bv1);
            float h2 = actf(acc[mg][ng][2] + bv0), h3 = actf(acc[mg][ng][3] + bv1);
            int wa = ra * PW + col / 2, wb = rb * PW + col / 2;
            sm[wa] = pack_hi(h0, h1); sm[A_LO + wa] = pack_lo(h0, h1);
            sm[wb] = pack_hi(h2, h3); sm[A_LO + wb] = pack_lo(h2, h3);
        }
    }
    __syncthreads();

    zero_acc(acc);
    kloop(sm, 26112, wr0, wc0, lane, acc);

#pragma unroll
    for (int mg = 0; mg < 2; mg++) {
        int ra = r0 + wr0 + mg * 16 + g, rb = ra + 8;
#pragma unroll
        for (int ng = 0; ng < 4; ng++) {
            int col = wc0 + ng * 8 + 2 * tig;
            float bv0 = b2[col], bv1 = b2[col + 1];
            if (ra < nrows) {
                float2 a = *(const float2*)(A + (size_t)ra * FDIM + col);
                *(float2*)(C + (size_t)ra * FDIM + col) =
                    make_float2(a.x + acc[mg][ng][0] + bv0, a.y + acc[mg][ng][1] + bv1);
            }
            if (rb < nrows) {
                float2 a = *(const float2*)(A + (size_t)rb * FDIM + col);
                *(float2*)(C + (size_t)rb * FDIM + col) =
                    make_float2(a.x + acc[mg][ng][2] + bv0, a.y + acc[mg][ng][3] + bv1);
            }
        }
    }
}

__global__ void __launch_bounds__(256, 1) gemm_dw_mma(
    const float* __restrict__ A, const uint32_t* __restrict__ w,
    const float* __restrict__ bias, const float* __restrict__ base,
    const float* __restrict__ uvec, float* __restrict__ C, int nrows) {
    extern __shared__ uint32_t sm[];
    const int tid = threadIdx.x, lane = tid & 31, wid = tid >> 5;
    const int wr0 = (wid >> 2) * 32, wc0 = (wid & 3) * 32;
    const int r0 = blockIdx.x * 64;
    const int g = lane >> 2, tig = lane & 3;

    conv_A<1>(A, sm, tid, r0, nrows);
    copy_mat(w, sm + 8704, tid);
    __syncthreads();

    float acc[2][4][4];
    zero_acc(acc);
    kloop(sm, 8704, wr0, wc0, lane, acc);

#pragma unroll
    for (int mg = 0; mg < 2; mg++) {
        int ra = r0 + wr0 + mg * 16 + g, rb = ra + 8;
#pragma unroll
        for (int ng = 0; ng < 4; ng++) {
            int col = wc0 + ng * 8 + 2 * tig;
            float bv0 = bias[col], bv1 = bias[col + 1];
            float u0 = uvec[col], u1 = uvec[col + 1];
            if (ra < nrows) {
                float2 x = *(const float2*)(base + (size_t)ra * FDIM + col);
                *(float2*)(C + (size_t)ra * FDIM + col) =
                    make_float2(u0 * x.x + acc[mg][ng][0] + bv0, u1 * x.y + acc[mg][ng][1] + bv1);
            }
            if (rb < nrows) {
                float2 x = *(const float2*)(base + (size_t)rb * FDIM + col);
                *(float2*)(C + (size_t)rb * FDIM + col) =
                    make_float2(u0 * x.x + acc[mg][ng][2] + bv0, u1 * x.y + acc[mg][ng][3] + bv1);
            }
        }
    }
}

// ---- fused weight conversion: all 75 matrices in one launch ----
struct WSrc { const float* p[9]; };

__global__ void conv_weights_all(WSrc s, uint32_t* __restrict__ dst) {
    int gid = blockIdx.x * blockDim.x + threadIdx.x;
    if (gid >= 75 * 16384) return;
    int m = gid >> 14, e = gid & 16383;
    int grp, loc;
    if      (m < 5)  { grp = 0; loc = m; }
    else if (m < 10) { grp = 1; loc = m - 5; }
    else if (m < 25) { grp = 2; loc = m - 10; }
    else if (m < 40) { grp = 3; loc = m - 25; }
    else if (m < 45) { grp = 4; loc = m - 40; }
    else if (m < 55) { grp = 5; loc = m - 45; }
    else if (m < 65) { grp = 6; loc = m - 55; }
    else if (m < 70) { grp = 7; loc = m - 65; }
    else             { grp = 8; loc = m - 70; }
    float x = s.p[grp][loc * 16384 + e];
    int k = e >> 7, n = e & 127;
    __nv_bfloat16 hi = __float2bfloat16(x);
    __nv_bfloat16 lo = __float2bfloat16(x - __bfloat162float(hi));
    char* bp = (char*)(dst + (size_t)m * MATW);
    *(__nv_bfloat16*)(bp + n * 272 + k * 2)         = hi;
    *(__nv_bfloat16*)(bp + 34816 + n * 272 + k * 2) = lo;
}

// ---- k2f conversion: [5][64][128] fp32 -> padded [n][k] bf16 hi/lo planes ----
__global__ void conv_k2f(const float* __restrict__ src, uint32_t* __restrict__ dst) {
    int gid = blockIdx.x * blockDim.x + threadIdx.x;
    if (gid >= 5 * 4096) return;
    int b = gid >> 12, r = gid & 4095;
    int n = r >> 5, w = r & 31;
    const float* s = src + b * 8192;
    float x0 = s[(2 * w) * 128 + n], x1 = s[(2 * w + 1) * 128 + n];
    dst[b * 9216 + n * MPW + w]        = pack_hi(x0, x1);
    dst[b * 9216 + 4608 + n * MPW + w] = pack_lo(x0, x1);
}

// ---------------- init: x = embeddings[Z] ----------------
__global__ void init_kernel(const int* __restrict__ Z, const float* __restrict__ emb,
                            float* __restrict__ x) {
    int idx = blockIdx.x * blockDim.x + threadIdx.x;
    if (idx < NATOMS * FDIM) {
        int n = idx >> 7, f = idx & 127;
        x[idx] = emb[Z[n] * FDIM + f];
    }
}

// ---------------- pair: Dij + rbf (bf16 hi/lo planes) ----------------
__global__ void pair_kernel(const float* __restrict__ R, const int* __restrict__ idx_i,
                            const int* __restrict__ idx_j, const float* __restrict__ cent,
                            const float* __restrict__ wid,
                            uint32_t* __restrict__ rbfh, uint32_t* __restrict__ rbfl,
                            float* __restrict__ Dij_out) {
    int gid = blockIdx.x * blockDim.x + threadIdx.x;
    int p = gid >> 5, w = gid & 31;
    if (p >= NPAIRS) return;
    int i = idx_i[p], j = idx_j[p];
    float dx = R[i * 3 + 0] - R[j * 3 + 0];
    float dy = R[i * 3 + 1] - R[j * 3 + 1];
    float dz = R[i * 3 + 2] - R[j * 3 + 2];
    float D = sqrtf(fmaxf(dx * dx + dy * dy + dz * dz, 0.f));
    if (w == 0) Dij_out[p] = D;
    float xr = D * 0.1f;
    float cut = 0.f;
    if (xr < 1.f) {
        float x3 = xr * xr * xr, x4 = x3 * xr, x5 = x4 * xr;
        cut = 1.f - 6.f * x5 + 15.f * x4 - 10.f * x3;
    }
    float ed = __expf(-D);
    float t0 = ed - cent[2 * w],     t1 = ed - cent[2 * w + 1];
    float r0 = cut * __expf(-wid[2 * w] * t0 * t0);
    float r1 = cut * __expf(-wid[2 * w + 1] * t1 * t1);
    rbfh[p * 32 + w] = pack_hi(r0, r1);
    rbfl[p * 32 + w] = pack_lo(r0, r1);
}

// ---------------- message via MMA: m[idx_i] += (rbf @ k2f) * xj[idx_j] ----------------
__global__ void __launch_bounds__(256, 2) message_mma(
    const uint32_t* __restrict__ rbfh, const uint32_t* __restrict__ rbfl,
    const uint32_t* __restrict__ k2f, const float* __restrict__ xj,
    const int* __restrict__ idx_i, const int* __restrict__ idx_j,
    float* __restrict__ m) {
    extern __shared__ uint32_t sm[];
    float* gf = (float*)(sm + OFF_G);
    const int tid = threadIdx.x, lane = tid & 31, wid = tid >> 5;
    const int g = lane >> 2, tig = lane & 3;
    const int wr0 = (wid >> 2) * 32, wc0 = (wid & 3) * 32;

    {   // k2f planes: 9216 words = 2304 uint4
        const uint4* kv = (const uint4*)k2f;
        uint4* sv = (uint4*)sm;
#pragma unroll
        for (int i = 0; i < 9; i++) sv[tid + i * 256] = kv[tid + i * 256];
    }

    for (int ch = blockIdx.x; ch < NCH; ch += gridDim.x) {
        const int p0 = ch * 64;
        __syncthreads();   // prev epilogue g-reads done; prev MMA rbf-reads done
        {   // rbf planes: 64 rows x 32 words each
#pragma unroll
            for (int i = 0; i < 8; i++) {
                int v = tid + i * 256;
                int r = v >> 5, w = v & 31;
                sm[OFF_RBFH + r * MPW + w] = rbfh[p0 * 32 + v];
                sm[OFF_RBFL + r * MPW + w] = rbfl[p0 * 32 + v];
            }
        }
        __syncthreads();

        float acc[2][4][4];
        zero_acc(acc);
#pragma unroll
        for (int ks = 0; ks < 4; ks++) {
            const int kw = ks * 8 + tig;
            uint32_t ah[2][4], al[2][4];
#pragma unroll
            for (int mg = 0; mg < 2; mg++) {
                int ba = OFF_RBFH + (wr0 + mg * 16 + g) * MPW + kw;
                ah[mg][0] = sm[ba];            ah[mg][1] = sm[ba + 8 * MPW];
                ah[mg][2] = sm[ba + 4];        ah[mg][3] = sm[ba + 8 * MPW + 4];
                int bb = ba + (OFF_RBFL - OFF_RBFH);
                al[mg][0] = sm[bb];            al[mg][1] = sm[bb + 8 * MPW];
                al[mg][2] = sm[bb + 4];        al[mg][3] = sm[bb + 8 * MPW + 4];
            }
#pragma unroll
            for (int ng = 0; ng < 4; ng++) {
                int nb = OFF_K2FH + (wc0 + ng * 8 + g) * MPW + kw;
                uint32_t bh[2] = { sm[nb],        sm[nb + 4] };
                uint32_t bl[2] = { sm[nb + 4608], sm[nb + 4608 + 4] };
#pragma unroll
                for (int mg = 0; mg < 2; mg++) {
                    mma_bf16(acc[mg][ng], ah[mg], bh);
                    mma_bf16(acc[mg][ng], ah[mg], bl);
                    mma_bf16(acc[mg][ng], al[mg], bh);
                }
            }
        }

        // stage g through smem
#pragma unroll
        for (int mg = 0; mg < 2; mg++) {
            int row = wr0 + mg * 16 + g;
#pragma unroll
            for (int ng = 0; ng < 4; ng++) {
                int col = wc0 + ng * 8 + 2 * tig;
                *(float2*)&gf[row * 132 + col]       = make_float2(acc[mg][ng][0], acc[mg][ng][1]);
                *(float2*)&gf[(row + 8) * 132 + col] = make_float2(acc[mg][ng][2], acc[mg][ng][3]);
            }
        }
        __syncthreads();

        // epilogue: warp w handles pairs w*8 .. w*8+7
#pragma unroll
        for (int q = 0; q < 8; q++) {
            int r = wid * 8 + q, p = p0 + r;
            int i = idx_i[p], j = idx_j[p];
            float4 gv = *(const float4*)&gf[r * 132 + lane * 4];
            float4 xv = *(const float4*)(xj + (size_t)j * FDIM + lane * 4);
            red_add_f4(m + (size_t)i * FDIM + lane * 4,
                       make_float4(gv.x * xv.x, gv.y * xv.y, gv.z * xv.z, gv.w * xv.w));
        }
    }
}

// ---------------- output block ----------------
__global__ void outblock_kernel(const float* __restrict__ o, const float* __restrict__ ow,
                                float* __restrict__ Ea, float* __restrict__ Qa,
                                float* __restrict__ last2, float* __restrict__ nh, int bpos) {
    int n = blockIdx.x, tid = threadIdx.x;
    float a = actf(o[n * FDIM + tid]);
    float e = a * ow[tid * 2], q = a * ow[tid * 2 + 1];
#pragma unroll
    for (int s = 16; s; s >>= 1) {
        e += __shfl_xor_sync(0xffffffffu, e, s);
        q += __shfl_xor_sync(0xffffffffu, q, s);
    }
    __shared__ float se[4], sq[4];
    if ((tid & 31) == 0) { se[tid >> 5] = e; sq[tid >> 5] = q; }
    __syncthreads();
    if (tid == 0) {
        e = se[0] + se[1] + se[2] + se[3];
        q = sq[0] + sq[1] + sq[2] + sq[3];
        Ea[n] += e; Qa[n] += q;
        float e2 = e * e, q2 = q * q;
        if (bpos) {
            float le = last2[2 * n], lq = last2[2 * n + 1];
            atomicAdd(nh, e2 / (e2 + le + 1e-7f) + q2 / (q2 + lq + 1e-7f));
        }
        last2[2 * n] = e2; last2[2 * n + 1] = q2;
    }
}

// ---------------- final ----------------
__global__ void final_kernel(const int* __restrict__ Z, const float* __restrict__ Ea,
                             const float* __restrict__ Qa, const float* __restrict__ nh,
                             const float* __restrict__ Es, const float* __restrict__ Eh,
                             const float* __restrict__ Qs, const float* __restrict__ Qh,
                             float* __restrict__ out) {
    int n = blockIdx.x * blockDim.x + threadIdx.x;
    if (n < NATOMS) {
        int z = Z[n];
        out[n]          = Es[z] * Ea[n] + Eh[z];
        out[NATOMS + n] = Qs[z] * Qa[n] + Qh[z];
    }
    if (n == 0) out[2 * NATOMS + NPAIRS] = *nh / (2.f * NATOMS);
}

// ---------------- launch ----------------
extern "C" void kernel_launch(void* const* d_in, const int* in_sizes, int n_in,
                              void* d_out, int out_size) {
    const int*   Z      = (const int*)  d_in[0];
    const float* R      = (const float*)d_in[1];
    const int*   idx_i  = (const int*)  d_in[2];
    const int*   idx_j  = (const int*)  d_in[3];
    const float* emb    = (const float*)d_in[4];
    const float* cent   = (const float*)d_in[5];
    const float* wid    = (const float*)d_in[6];
    const float* k2f    = (const float*)d_in[7];
    const float* Wi     = (const float*)d_in[8];
    const float* bi     = (const float*)d_in[9];
    const float* Wj     = (const float*)d_in[10];
    const float* bj     = (const float*)d_in[11];
    const float* riW1   = (const float*)d_in[12];
    const float* rib1   = (const float*)d_in[13];
    const float* riW2   = (const float*)d_in[14];
    const float* rib2   = (const float*)d_in[15];
    const float* dW     = (const float*)d_in[16];
    const float* db     = (const float*)d_in[17];
    const float* u      = (const float*)d_in[18];
    const float* raW1   = (const float*)d_in[19];
    const float* rab1   = (const float*)d_in[20];
    const float* raW2   = (const float*)d_in[21];
    const float* rab2   = (const float*)d_in[22];
    const float* roW1   = (const float*)d_in[23];
    const float* rob1   = (const float*)d_in[24];
    const float* roW2   = (const float*)d_in[25];
    const float* rob2   = (const float*)d_in[26];
    const float* outW   = (const float*)d_in[27];
    const float* Escale = (const float*)d_in[28];
    const float* Eshift = (const float*)d_in[29];
    const float* Qscale = (const float*)d_in[30];
    const float* Qshift = (const float*)d_in[31];
    float* out = (float*)d_out;

    float *x, *xjb, *m, *o, *Ea, *Qa, *l2, *nh;
    uint32_t *wbf, *rbfh, *rbfl, *k2fb;
    cudaGetSymbolAddress((void**)&rbfh, g_rbfh);
    cudaGetSymbolAddress((void**)&rbfl, g_rbfl);
    cudaGetSymbolAddress((void**)&k2fb, g_k2fb);
    cudaGetSymbolAddress((void**)&x,   g_x);
    cudaGetSymbolAddress((void**)&xjb, g_xj);
    cudaGetSymbolAddress((void**)&m,   g_m);
    cudaGetSymbolAddress((void**)&o,   g_o);
    cudaGetSymbolAddress((void**)&Ea,  g_Ea);
    cudaGetSymbolAddress((void**)&Qa,  g_Qa);
    cudaGetSymbolAddress((void**)&l2,  g_l2);
    cudaGetSymbolAddress((void**)&nh,  g_nh);
    cudaGetSymbolAddress((void**)&wbf, g_wbf);

    cudaFuncSetAttribute(gemm_dual_mma,  cudaFuncAttributeMaxDynamicSharedMemorySize, SM_DUAL);
    cudaFuncSetAttribute(gemm_resid_mma, cudaFuncAttributeMaxDynamicSharedMemorySize, SM_RES);
    cudaFuncSetAttribute(gemm_dw_mma,    cudaFuncAttributeMaxDynamicSharedMemorySize, SM_DW);
    cudaFuncSetAttribute(message_mma,    cudaFuncAttributeMaxDynamicSharedMemorySize, SM_MSG);

    cudaMemsetAsync(Ea, 0, NATOMS * sizeof(float));
    cudaMemsetAsync(Qa, 0, NATOMS * sizeof(float));
    cudaMemsetAsync(nh, 0, sizeof(float));

    // weight slots: Wi:0..4  Wj:5..9  riW1:10..24  riW2:25..39  dW:40..44
    // raW1:45..54  raW2:55..64  roW1:65..69  roW2:70..74
    WSrc ws;
    ws.p[0] = Wi;   ws.p[1] = Wj;   ws.p[2] = riW1; ws.p[3] = riW2; ws.p[4] = dW;
    ws.p[5] = raW1; ws.p[6] = raW2; ws.p[7] = roW1; ws.p[8] = roW2;
    conv_weights_all<<<(75 * 16384 + 255) / 256, 256>>>(ws, wbf);
    conv_k2f<<<(5 * 4096 + 255) / 256, 256>>>(k2f, k2fb);

    init_kernel<<<(NATOMS * FDIM + 255) / 256, 256>>>(Z, emb, x);
    pair_kernel<<<(NPAIRS * 32 + 255) / 256, 256>>>(R, idx_i, idx_j, cent, wid,
                                                    rbfh, rbfl, out + 2 * NATOMS);

    const int GB = (NATOMS + 63) / 64;  // 157
    auto WS = [&](int s) { return (const uint32_t*)(wbf + (size_t)s * MATW); };

    for (int b = 0; b < NB; b++) {
        gemm_dual_mma<<<GB, 256, SM_DUAL>>>(x, WS(0 + b), WS(5 + b),
                                            bi + b * 128, bj + b * 128, m, xjb, NATOMS);
        message_mma<<<296, 256, SM_MSG>>>(rbfh, rbfl, k2fb + (size_t)b * 9216,
                                          xjb, idx_i, idx_j, m);
        for (int l = 0; l < NRI; l++) {
            int wdx = b * NRI + l;
            gemm_resid_mma<<<GB, 256, SM_RES>>>(m, WS(10 + wdx), WS(25 + wdx),
                                                rib1 + wdx * 128, rib2 + wdx * 128, m, NATOMS);
        }
        gemm_dw_mma<<<GB, 256, SM_DW>>>(m, WS(40 + b), db + b * 128, x, u + b * 128, x, NATOMS);
        for (int l = 0; l < NRA; l++) {
            int wdx = b * NRA + l;
            gemm_resid_mma<<<GB, 256, SM_RES>>>(x, WS(45 + wdx), WS(55 + wdx),
                                                rab1 + wdx * 128, rab2 + wdx * 128, x, NATOMS);
        }
        gemm_resid_mma<<<GB, 256, SM_RES>>>(x, WS(65 + b), WS(70 + b),
                                            rob1 + b * 128, rob2 + b * 128, o, NATOMS);
        outblock_kernel<<<NATOMS, 128>>>(o, outW + b * FDIM * 2, Ea, Qa, l2, nh, b);
    }
    final_kernel<<<(NATOMS + 255) / 256, 256>>>(Z, Ea, Qa, nh, Escale, Eshift,
                                                Qscale, Qshift, out);
}